// round 1
// baseline (speedup 1.0000x reference)
#include <cuda_runtime.h>

#define NN 400
#define FF 240
#define CC 32
#define LL 1440
#define SIN_X2 480   // row index of swE in sw; swEt at 481

// ---- scratch (device globals; no allocation allowed) ----
__device__ float g_Xi[NN * CC];
__device__ float g_Xj[NN * CC];
__device__ float g_aggI[NN * CC];
__device__ float g_aggJ[NN * CC];
__device__ float g_e1[NN * NN];
__device__ float g_x1[NN * FF];
__device__ float g_x2[NN * FF];

// ============================================================
// K1: Xi = x @ sw[0:F] + sb,  Xj = x @ sw[F:2F]
// block = 256 thr (8 warps), handles 4 node rows; warps 0-3 -> Xi, 4-7 -> Xj
// ============================================================
__global__ void __launch_bounds__(256) xw_kernel(
    const float* __restrict__ xin, const float* __restrict__ sw,
    const float* __restrict__ sb, int useX1)
{
    const float* x = useX1 ? g_x1 : xin;
    __shared__ __align__(16) float sx[4][FF];
    int row0 = blockIdx.x * 4;
    for (int idx = threadIdx.x; idx < 4 * FF; idx += blockDim.x)
        sx[idx / FF][idx % FF] = x[row0 * FF + idx];
    __syncthreads();

    int w = threadIdx.x >> 5, c = threadIdx.x & 31;
    int r = w & 3;
    bool isJ = (w >= 4);
    const float* wb = sw + (isJ ? FF * CC : 0);
    float acc = isJ ? 0.f : sb[c];
    const float4* sxr = (const float4*)sx[r];
#pragma unroll 5
    for (int f4 = 0; f4 < FF / 4; f4++) {
        float4 xv = sxr[f4];
        int f = f4 * 4;
        acc += xv.x * wb[(f + 0) * CC + c];
        acc += xv.y * wb[(f + 1) * CC + c];
        acc += xv.z * wb[(f + 2) * CC + c];
        acc += xv.w * wb[(f + 3) * CC + c];
    }
    (isJ ? g_Xj : g_Xi)[(row0 + r) * CC + c] = acc;
}

// ============================================================
// K2: per-pair kernel. Grid = 800 blocks:
//   blocks [0,400)   : row mode  (fixed i, loop j) -> aggI, e_out(layer1)
//   blocks [400,800) : col mode  (fixed j, loop i) -> aggJ
// Each thread owns whole pairs (t[0..31] in regs), so the three
// 32-dots are serial FMAs, no shuffles in the hot loop.
// ============================================================
__global__ void __launch_bounds__(128) pair_kernel(
    const float* __restrict__ eParam, const float* __restrict__ a,
    const float* __restrict__ sw,
    const float* __restrict__ aiw, const float* __restrict__ aib,
    const float* __restrict__ ajw, const float* __restrict__ ajb,
    const float* __restrict__ ew,  const float* __restrict__ eb,
    int layer)
{
    const float* e = (layer == 2) ? g_e1 : eParam;
    bool colMode = (blockIdx.x >= NN);
    int fixed = colMode ? (blockIdx.x - NN) : blockIdx.x;

    __shared__ __align__(16) float4 q[CC];  // (fixVec, swE, swEt, gateW)
    __shared__ float sEw[CC];
    __shared__ float sPart[4][CC];

    int tid = threadIdx.x;
    if (tid < CC) {
        float fx = colMode ? g_Xj[fixed * CC + tid] : g_Xi[fixed * CC + tid];
        float gw = colMode ? ajw[tid] : aiw[tid];
        q[tid] = make_float4(fx, sw[SIN_X2 * CC + tid], sw[(SIN_X2 + 1) * CC + tid], gw);
        sEw[tid] = ew[tid];
    }
    __syncthreads();

    float gb  = colMode ? ajb[0] : aib[0];
    float ebv = eb[0];
    bool writeE = (layer == 1) && !colMode;

    float acc[CC];
#pragma unroll
    for (int c = 0; c < CC; c++) acc[c] = 0.f;

    for (int v = tid; v < NN; v += 128) {
        int i = colMode ? v : fixed;
        int j = colMode ? fixed : v;
        float eij = __ldg(&e[i * NN + j]);
        float eji = __ldg(&e[j * NN + i]);
        float av  = __ldg(&a[i * NN + j]);
        const float4* vr = (const float4*)(colMode ? (g_Xi + v * CC) : (g_Xj + v * CC));

        float s = 0.f, se = 0.f;
        float tv[CC];
#pragma unroll
        for (int c4 = 0; c4 < CC / 4; c4++) {
            float4 vv = vr[c4];
            float vvals[4] = {vv.x, vv.y, vv.z, vv.w};
#pragma unroll
            for (int u = 0; u < 4; u++) {
                int c = c4 * 4 + u;
                float4 qq = q[c];
                float t = qq.x + vvals[u] + eij * qq.y + eji * qq.z;
                t = fmaxf(t, 0.f) * av;
                tv[c] = t;
                s  += t * qq.w;
                se += t * sEw[c];
            }
        }
        float gate = 1.f / (1.f + __expf(-(s + gb)));
#pragma unroll
        for (int c = 0; c < CC; c++) acc[c] += gate * tv[c];
        if (writeE) g_e1[fixed * NN + v] = se + ebv;
    }

    // block reduce: butterfly within warp, then 4 partials via shared
#pragma unroll
    for (int off = 16; off > 0; off >>= 1)
#pragma unroll
        for (int c = 0; c < CC; c++)
            acc[c] += __shfl_xor_sync(0xffffffffu, acc[c], off);
    int w = tid >> 5;
    if ((tid & 31) == 0) {
#pragma unroll
        for (int c = 0; c < CC; c++) sPart[w][c] = acc[c];
    }
    __syncthreads();
    if (tid < CC) {
        float r = sPart[0][tid] + sPart[1][tid] + sPart[2][tid] + sPart[3][tid];
        (colMode ? g_aggJ : g_aggI)[fixed * CC + tid] = r;
    }
}

// ============================================================
// K3: node model  x_out = [x, aggI, aggJ] @ nw + nb  (K=304, M=240)
// block = 256 thr, 4 node rows per block
// ============================================================
#define NK 304
__global__ void __launch_bounds__(256) node_kernel(
    const float* __restrict__ xin, const float* __restrict__ nw,
    const float* __restrict__ nb, int layer)
{
    const float* x = (layer == 1) ? xin : g_x1;
    float* xout = (layer == 1) ? g_x1 : g_x2;
    __shared__ __align__(16) float s[4][NK];
    int row0 = blockIdx.x * 4;
    for (int idx = threadIdx.x; idx < 4 * NK; idx += blockDim.x) {
        int r = idx / NK, k = idx % NK;
        float v;
        if (k < FF)            v = x[(row0 + r) * FF + k];
        else if (k < FF + CC)  v = g_aggI[(row0 + r) * CC + (k - FF)];
        else                   v = g_aggJ[(row0 + r) * CC + (k - FF - CC)];
        s[r][k] = v;
    }
    __syncthreads();

    int f = threadIdx.x;
    if (f < FF) {
        float b = nb[f];
        float a0 = b, a1 = b, a2 = b, a3 = b;
#pragma unroll 4
        for (int k4 = 0; k4 < NK / 4; k4++) {
            int k = k4 * 4;
            float w0 = nw[(k + 0) * FF + f];
            float w1 = nw[(k + 1) * FF + f];
            float w2 = nw[(k + 2) * FF + f];
            float w3 = nw[(k + 3) * FF + f];
            float4 x0 = *(const float4*)&s[0][k];
            float4 x1 = *(const float4*)&s[1][k];
            float4 x2 = *(const float4*)&s[2][k];
            float4 x3 = *(const float4*)&s[3][k];
            a0 += x0.x * w0 + x0.y * w1 + x0.z * w2 + x0.w * w3;
            a1 += x1.x * w0 + x1.y * w1 + x1.z * w2 + x1.w * w3;
            a2 += x2.x * w0 + x2.y * w1 + x2.z * w2 + x2.w * w3;
            a3 += x3.x * w0 + x3.y * w1 + x3.z * w2 + x3.w * w3;
        }
        xout[(row0 + 0) * FF + f] = a0;
        xout[(row0 + 1) * FF + f] = a1;
        xout[(row0 + 2) * FF + f] = a2;
        xout[(row0 + 3) * FF + f] = a3;
    }
}

// ============================================================
// K4: out = x2 @ dw + db   (400 x 1440, K=240)
// block = 256 thr, 8 rows x 256 cols tile; grid (6, 50)
// ============================================================
__global__ void __launch_bounds__(256) out_kernel(
    const float* __restrict__ dw, const float* __restrict__ db,
    float* __restrict__ out)
{
    __shared__ __align__(16) float s[8][FF];
    int row0 = blockIdx.y * 8;
    int col = blockIdx.x * blockDim.x + threadIdx.x;
    for (int idx = threadIdx.x; idx < 8 * FF; idx += blockDim.x)
        s[idx / FF][idx % FF] = g_x2[row0 * FF + idx];
    __syncthreads();
    if (col >= LL) return;

    float b = db[col];
    float acc[8];
#pragma unroll
    for (int r = 0; r < 8; r++) acc[r] = b;

#pragma unroll 2
    for (int k4 = 0; k4 < FF / 4; k4++) {
        int k = k4 * 4;
        float w0 = dw[(k + 0) * LL + col];
        float w1 = dw[(k + 1) * LL + col];
        float w2 = dw[(k + 2) * LL + col];
        float w3 = dw[(k + 3) * LL + col];
#pragma unroll
        for (int r = 0; r < 8; r++) {
            float4 xv = *(const float4*)&s[r][k];
            acc[r] += xv.x * w0 + xv.y * w1 + xv.z * w2 + xv.w * w3;
        }
    }
#pragma unroll
    for (int r = 0; r < 8; r++)
        out[(row0 + r) * LL + col] = acc[r];
}

// ============================================================
extern "C" void kernel_launch(void* const* d_in, const int* in_sizes, int n_in,
                              void* d_out, int out_size)
{
    const float* x      = (const float*)d_in[0];
    const float* a      = (const float*)d_in[1];
    const float* e      = (const float*)d_in[2];
    const float* c1_sw  = (const float*)d_in[3];
    const float* c1_sb  = (const float*)d_in[4];
    const float* c1_aiw = (const float*)d_in[5];
    const float* c1_aib = (const float*)d_in[6];
    const float* c1_ajw = (const float*)d_in[7];
    const float* c1_ajb = (const float*)d_in[8];
    const float* c1_nw  = (const float*)d_in[9];
    const float* c1_nb  = (const float*)d_in[10];
    const float* c1_ew  = (const float*)d_in[11];
    const float* c1_eb  = (const float*)d_in[12];
    const float* c2_sw  = (const float*)d_in[13];
    const float* c2_sb  = (const float*)d_in[14];
    const float* c2_aiw = (const float*)d_in[15];
    const float* c2_aib = (const float*)d_in[16];
    const float* c2_ajw = (const float*)d_in[17];
    const float* c2_ajb = (const float*)d_in[18];
    const float* c2_nw  = (const float*)d_in[19];
    const float* c2_nb  = (const float*)d_in[20];
    const float* c2_ew  = (const float*)d_in[21];
    const float* c2_eb  = (const float*)d_in[22];
    const float* dw     = (const float*)d_in[23];
    const float* db     = (const float*)d_in[24];
    float* out = (float*)d_out;

    // ---- layer 1 ----
    xw_kernel<<<NN / 4, 256>>>(x, c1_sw, c1_sb, 0);
    pair_kernel<<<2 * NN, 128>>>(e, a, c1_sw, c1_aiw, c1_aib, c1_ajw, c1_ajb,
                                 c1_ew, c1_eb, 1);
    node_kernel<<<NN / 4, 256>>>(x, c1_nw, c1_nb, 1);

    // ---- layer 2 (e input = g_e1; e_out not needed) ----
    xw_kernel<<<NN / 4, 256>>>(nullptr, c2_sw, c2_sb, 1);
    pair_kernel<<<2 * NN, 128>>>(nullptr, a, c2_sw, c2_aiw, c2_aib, c2_ajw, c2_ajb,
                                 c2_ew, c2_eb, 2);
    node_kernel<<<NN / 4, 256>>>(nullptr, c2_nw, c2_nb, 2);

    // ---- readout ----
    out_kernel<<<dim3((LL + 255) / 256, NN / 8), 256>>>(dw, db, out);
}